// round 1
// baseline (speedup 1.0000x reference)
#include <cuda_runtime.h>
#include <cstdint>

// Problem constants (fixed by the reference: B=2, V=2000, F=800, 128x128, K=4)
#define IMG     128
#define NPIX    (IMG * IMG)          // 16384 pixels per image
#define NFACE   800
#define NB      2
#define NV      2000
#define KTOP    4
#define EPSF    1e-8f
#define BLURF   0.01f
#define FSTRIDE 20                   // floats per face record (5 x float4)
#define SMEM_BYTES (NFACE * FSTRIDE * 4)   // 64000 bytes

// Output layout (float32, concatenated flattened reference outputs):
//   [0          , 131072)  pix_to_face  (B,H,W,K)
//   [131072     , 262144)  zbuf         (B,H,W,K)
//   [262144     , 655360)  bary         (B,H,W,K,3)
//   [655360     , 786432)  dist         (B,H,W,K)
#define OFF_ZBUF  131072
#define OFF_BARY  262144
#define OFF_DIST  655360

struct FaceEval {
    float b0, b1, b2, zpix, dsign;
    bool  valid;
};

// Bit-exact replica of reference _seg_dist2 inner math.
// ref: t = clip( sum(pa*ab) / (sum(ab*ab)+EPS), 0, 1 ); d = pa - t*ab; return sum(d*d)
// (sum(ab*ab)+EPS) is precomputed per face as l.
__device__ __forceinline__ float seg_dist2(float pax, float pay,
                                           float abx, float aby, float l) {
    float num = __fadd_rn(__fmul_rn(pax, abx), __fmul_rn(pay, aby));
    float t   = num / l;                          // IEEE correctly-rounded div
    t = fminf(fmaxf(t, 0.0f), 1.0f);
    float dx = __fsub_rn(pax, __fmul_rn(t, abx));
    float dy = __fsub_rn(pay, __fmul_rn(t, aby));
    return __fadd_rn(__fmul_rn(dx, dx), __fmul_rn(dy, dy));
}

// Evaluate one face at pixel (px,py). fq5 points at 5 float4s of per-face data.
// Field map:
//  q0: a0x a0y a1x a1y
//  q1: a2x a2y dx01 dy01
//  q2: dx12 dy12 dx20 dy20
//  q3: z0 z1 z2 denom
//  q4: l01 l12 l20 areaflag
__device__ __forceinline__ FaceEval eval_face(const float4* __restrict__ fq5,
                                              float px, float py) {
    float4 q0 = fq5[0];
    float4 q1 = fq5[1];
    float4 q2 = fq5[2];
    float4 q3 = fq5[3];
    float4 q4 = fq5[4];

    float pa0x = __fsub_rn(px, q0.x), pa0y = __fsub_rn(py, q0.y);
    float pa1x = __fsub_rn(px, q0.z), pa1y = __fsub_rn(py, q0.w);
    float pa2x = __fsub_rn(px, q1.x), pa2y = __fsub_rn(py, q1.y);

    // w0 = edge(a1,a2,p) = (px-a1x)*dy12 - (py-a1y)*dx12   (dy12 = a2y-a1y, dx12 = a2x-a1x)
    float w0 = __fsub_rn(__fmul_rn(pa1x, q2.y), __fmul_rn(pa1y, q2.x));
    // w1 = edge(a2,a0,p) = (px-a2x)*dy20 - (py-a2y)*dx20
    float w1 = __fsub_rn(__fmul_rn(pa2x, q2.w), __fmul_rn(pa2y, q2.z));
    // w2 = edge(a0,a1,p) = (px-a0x)*dy01 - (py-a0y)*dx01
    float w2 = __fsub_rn(__fmul_rn(pa0x, q1.w), __fmul_rn(pa0y, q1.z));

    FaceEval e;
    float denom = q3.w;
    e.b0 = w0 / denom;
    e.b1 = w1 / denom;
    e.b2 = w2 / denom;

    // zpix = (b0*z0 + b1*z1) + b2*z2  (left-to-right as in the reference)
    e.zpix = __fadd_rn(__fadd_rn(__fmul_rn(e.b0, q3.x), __fmul_rn(e.b1, q3.y)),
                       __fmul_rn(e.b2, q3.z));

    bool inside = (e.b0 >= 0.0f) && (e.b1 >= 0.0f) && (e.b2 >= 0.0f);

    float d01 = seg_dist2(pa0x, pa0y, q1.z, q1.w, q4.x);  // seg(a0,a1)
    float d12 = seg_dist2(pa1x, pa1y, q2.x, q2.y, q4.y);  // seg(a1,a2)
    float d20 = seg_dist2(pa2x, pa2y, q2.z, q2.w, q4.z);  // seg(a2,a0)
    float dmin = fminf(d01, fminf(d12, d20));

    e.dsign = inside ? -dmin : dmin;
    e.valid = (inside || (dmin < BLURF)) && (e.zpix > EPSF) && (q4.w > 0.5f);
    return e;
}

__global__ void __launch_bounds__(256, 1)
raster_kernel(const float* __restrict__ verts,
              const int*   __restrict__ faces,
              float*       __restrict__ out) {
    extern __shared__ float sf[];
    const int b   = blockIdx.y;
    const int tid = threadIdx.x;

    // ---- Phase 1: build per-face records in shared memory (bit-exact derived terms)
    const float* vb = verts + (size_t)b * NV * 3;
    for (int f = tid; f < NFACE; f += blockDim.x) {
        int i0 = faces[3 * f + 0];
        int i1 = faces[3 * f + 1];
        int i2 = faces[3 * f + 2];
        float a0x = vb[3 * i0], a0y = vb[3 * i0 + 1], z0 = vb[3 * i0 + 2];
        float a1x = vb[3 * i1], a1y = vb[3 * i1 + 1], z1 = vb[3 * i1 + 2];
        float a2x = vb[3 * i2], a2y = vb[3 * i2 + 1], z2 = vb[3 * i2 + 2];

        float dx01 = __fsub_rn(a1x, a0x), dy01 = __fsub_rn(a1y, a0y);
        float dx12 = __fsub_rn(a2x, a1x), dy12 = __fsub_rn(a2y, a1y);
        float dx20 = __fsub_rn(a0x, a2x), dy20 = __fsub_rn(a0y, a2y);

        // area = edge(a0,a1,a2) = (a2x-a0x)*dy01 - (a2y-a0y)*dx01
        float area = __fsub_rn(__fmul_rn(__fsub_rn(a2x, a0x), dy01),
                               __fmul_rn(__fsub_rn(a2y, a0y), dx01));
        bool  big   = fabsf(area) > EPSF;
        float denom = big ? area : ((area >= 0.0f) ? EPSF : -EPSF);

        float l01 = __fadd_rn(__fadd_rn(__fmul_rn(dx01, dx01), __fmul_rn(dy01, dy01)), EPSF);
        float l12 = __fadd_rn(__fadd_rn(__fmul_rn(dx12, dx12), __fmul_rn(dy12, dy12)), EPSF);
        float l20 = __fadd_rn(__fadd_rn(__fmul_rn(dx20, dx20), __fmul_rn(dy20, dy20)), EPSF);

        float* d = sf + f * FSTRIDE;
        d[0]  = a0x;  d[1]  = a0y;  d[2]  = a1x;  d[3]  = a1y;
        d[4]  = a2x;  d[5]  = a2y;  d[6]  = dx01; d[7]  = dy01;
        d[8]  = dx12; d[9]  = dy12; d[10] = dx20; d[11] = dy20;
        d[12] = z0;   d[13] = z1;   d[14] = z2;   d[15] = denom;
        d[16] = l01;  d[17] = l12;  d[18] = l20;  d[19] = big ? 1.0f : 0.0f;
    }
    __syncthreads();

    // ---- Phase 2: one pixel per thread, scan all faces, keep top-4 smallest z
    const int pix = blockIdx.x * 256 + tid;     // 0..16383
    const int pi  = pix >> 7;                    // row
    const int pj  = pix & (IMG - 1);             // col
    // px = 1 - 2*(j+0.5)/128 : exact in fp32 regardless of op order
    const float px = 1.0f - (2.0f * ((float)pj + 0.5f)) * (1.0f / (float)IMG);
    const float py = 1.0f - (2.0f * ((float)pi + 0.5f)) * (1.0f / (float)IMG);

    const float4* fq = (const float4*)sf;

    const unsigned long long SENT = ~0ull;
    unsigned long long s0 = SENT, s1 = SENT, s2 = SENT, s3 = SENT;

#pragma unroll 2
    for (int f = 0; f < NFACE; ++f) {
        FaceEval e = eval_face(fq + f * 5, px, py);
        // Packed key: valid z is > EPS > 0, so float bits are order-isomorphic.
        // Low 32 bits = face index -> exact lower-index-first tie-break of top_k.
        unsigned long long key =
            e.valid ? ((((unsigned long long)__float_as_uint(e.zpix)) << 32) |
                       (unsigned)f)
                    : SENT;
        bool c0 = key < s0, c1 = key < s1, c2 = key < s2, c3 = key < s3;
        unsigned long long n1 = c1 ? (c0 ? s0 : key) : s1;
        unsigned long long n2 = c2 ? (c1 ? s1 : key) : s2;
        unsigned long long n3 = c3 ? (c2 ? s2 : key) : s3;
        s0 = c0 ? key : s0;
        s1 = n1; s2 = n2; s3 = n3;
    }

    // ---- Phase 3: epilogue — recompute payload for the <=4 winners and store
    const long long gp = (long long)b * NPIX + pix;   // global pixel index
    unsigned long long ss[KTOP] = { s0, s1, s2, s3 };

#pragma unroll
    for (int k = 0; k < KTOP; ++k) {
        long long o = gp * KTOP + k;
        float p2f = -1.0f, zb = -1.0f, bb0 = -1.0f, bb1 = -1.0f, bb2 = -1.0f, ds = -1.0f;
        if (ss[k] != SENT) {
            int f = (int)(unsigned)(ss[k] & 0xffffffffu);
            FaceEval e = eval_face(fq + f * 5, px, py);
            p2f = (float)f;
            zb  = __uint_as_float((unsigned)(ss[k] >> 32));  // exact zpix bits
            bb0 = e.b0; bb1 = e.b1; bb2 = e.b2;
            ds  = e.dsign;
        }
        out[o]                 = p2f;
        out[OFF_ZBUF + o]      = zb;
        out[OFF_BARY + 3 * o]     = bb0;
        out[OFF_BARY + 3 * o + 1] = bb1;
        out[OFF_BARY + 3 * o + 2] = bb2;
        out[OFF_DIST + o]      = ds;
    }
}

extern "C" void kernel_launch(void* const* d_in, const int* in_sizes, int n_in,
                              void* d_out, int out_size) {
    const float* verts = (const float*)d_in[0];   // (2, 2000, 3) float32
    const int*   faces = (const int*)d_in[1];     // (800, 3)     int32
    float*       out   = (float*)d_out;

    // 64000 B dynamic smem > 48KB default: opt in (idempotent, host-side, capture-safe)
    cudaFuncSetAttribute(raster_kernel,
                         cudaFuncAttributeMaxDynamicSharedMemorySize, SMEM_BYTES);

    dim3 grid(NPIX / 256, NB);   // 64 x 2 blocks, 256 threads = 1 pixel/thread
    raster_kernel<<<grid, 256, SMEM_BYTES>>>(verts, faces, out);
}

// round 2
// speedup vs baseline: 2.0849x; 2.0849x over previous
#include <cuda_runtime.h>
#include <cstdint>

// Problem constants (fixed by the reference: B=2, V=2000, F=800, 128x128, K=4)
#define IMG     128
#define NPIX    (IMG * IMG)          // 16384 pixels per image
#define NFACE   800
#define NB      2
#define NV      2000
#define KTOP    4
#define EPSF    1e-8f
#define BLURF   0.01f
#define FSTRIDE 20                   // floats per face record (5 x float4)
#define SMEM_BYTES (NFACE * FSTRIDE * 4)   // 64000 bytes

#define TPB     224                  // 7 warps: 148 blocks * 7 warps ~= 1024 work-warps
#define BLKX    74                   // 74 * 224 = 16576 >= 16384 pixels per batch

// Output layout (float32, concatenated flattened reference outputs):
//   [0          , 131072)  pix_to_face  (B,H,W,K)
//   [131072     , 262144)  zbuf         (B,H,W,K)
//   [262144     , 655360)  bary         (B,H,W,K,3)
//   [655360     , 786432)  dist         (B,H,W,K)
#define OFF_ZBUF  131072
#define OFF_BARY  262144
#define OFF_DIST  655360

struct FaceEval {
    float b0, b1, b2, zpix, dsign;
    bool  valid;
};

// _seg_dist2 with per-face reciprocal rl = 1/(|ab|^2 + EPS) precomputed.
// t = clamp(num * rl, 0, 1); d = pa - t*ab; return |d|^2
__device__ __forceinline__ float seg_dist2(float pax, float pay,
                                           float abx, float aby, float rl) {
    float num = __fadd_rn(__fmul_rn(pax, abx), __fmul_rn(pay, aby));
    float t   = __fmul_rn(num, rl);
    t = fminf(fmaxf(t, 0.0f), 1.0f);
    float dx = __fsub_rn(pax, __fmul_rn(t, abx));
    float dy = __fsub_rn(pay, __fmul_rn(t, aby));
    return __fadd_rn(__fmul_rn(dx, dx), __fmul_rn(dy, dy));
}

// Field map (5 x float4 per face):
//  q0: a0x a0y a1x a1y
//  q1: a2x a2y dx01 dy01
//  q2: dx12 dy12 dx20 dy20
//  q3: z0 z1 z2 rdenom       (rdenom = 1/denom, correctly rounded, per-face)
//  q4: rl01 rl12 rl20 areaflag
__device__ __forceinline__ FaceEval eval_face(const float4* __restrict__ fq5,
                                              float px, float py) {
    float4 q0 = fq5[0];
    float4 q1 = fq5[1];
    float4 q2 = fq5[2];
    float4 q3 = fq5[3];
    float4 q4 = fq5[4];

    float pa0x = __fsub_rn(px, q0.x), pa0y = __fsub_rn(py, q0.y);
    float pa1x = __fsub_rn(px, q0.z), pa1y = __fsub_rn(py, q0.w);
    float pa2x = __fsub_rn(px, q1.x), pa2y = __fsub_rn(py, q1.y);

    float w0 = __fsub_rn(__fmul_rn(pa1x, q2.y), __fmul_rn(pa1y, q2.x));
    float w1 = __fsub_rn(__fmul_rn(pa2x, q2.w), __fmul_rn(pa2y, q2.z));
    float w2 = __fsub_rn(__fmul_rn(pa0x, q1.w), __fmul_rn(pa0y, q1.z));

    FaceEval e;
    float rd = q3.w;
    e.b0 = __fmul_rn(w0, rd);
    e.b1 = __fmul_rn(w1, rd);
    e.b2 = __fmul_rn(w2, rd);

    e.zpix = __fadd_rn(__fadd_rn(__fmul_rn(e.b0, q3.x), __fmul_rn(e.b1, q3.y)),
                       __fmul_rn(e.b2, q3.z));

    bool inside = (e.b0 >= 0.0f) && (e.b1 >= 0.0f) && (e.b2 >= 0.0f);

    float d01 = seg_dist2(pa0x, pa0y, q1.z, q1.w, q4.x);
    float d12 = seg_dist2(pa1x, pa1y, q2.x, q2.y, q4.y);
    float d20 = seg_dist2(pa2x, pa2y, q2.z, q2.w, q4.z);
    float dmin = fminf(d01, fminf(d12, d20));

    e.dsign = inside ? -dmin : dmin;
    e.valid = (inside || (dmin < BLURF)) && (e.zpix > EPSF) && (q4.w > 0.5f);
    return e;
}

__global__ void __launch_bounds__(TPB, 1)
raster_kernel(const float* __restrict__ verts,
              const int*   __restrict__ faces,
              float*       __restrict__ out) {
    extern __shared__ float sf[];
    const int b   = blockIdx.y;
    const int tid = threadIdx.x;

    // ---- Phase 1: per-face records in shared memory (divisions done HERE, once per face)
    const float* vb = verts + (size_t)b * NV * 3;
    for (int f = tid; f < NFACE; f += TPB) {
        int i0 = faces[3 * f + 0];
        int i1 = faces[3 * f + 1];
        int i2 = faces[3 * f + 2];
        float a0x = vb[3 * i0], a0y = vb[3 * i0 + 1], z0 = vb[3 * i0 + 2];
        float a1x = vb[3 * i1], a1y = vb[3 * i1 + 1], z1 = vb[3 * i1 + 2];
        float a2x = vb[3 * i2], a2y = vb[3 * i2 + 1], z2 = vb[3 * i2 + 2];

        float dx01 = __fsub_rn(a1x, a0x), dy01 = __fsub_rn(a1y, a0y);
        float dx12 = __fsub_rn(a2x, a1x), dy12 = __fsub_rn(a2y, a1y);
        float dx20 = __fsub_rn(a0x, a2x), dy20 = __fsub_rn(a0y, a2y);

        float area = __fsub_rn(__fmul_rn(__fsub_rn(a2x, a0x), dy01),
                               __fmul_rn(__fsub_rn(a2y, a0y), dx01));
        bool  big   = fabsf(area) > EPSF;
        float denom = big ? area : ((area >= 0.0f) ? EPSF : -EPSF);

        float l01 = __fadd_rn(__fadd_rn(__fmul_rn(dx01, dx01), __fmul_rn(dy01, dy01)), EPSF);
        float l12 = __fadd_rn(__fadd_rn(__fmul_rn(dx12, dx12), __fmul_rn(dy12, dy12)), EPSF);
        float l20 = __fadd_rn(__fadd_rn(__fmul_rn(dx20, dx20), __fmul_rn(dy20, dy20)), EPSF);

        float* d = sf + f * FSTRIDE;
        d[0]  = a0x;  d[1]  = a0y;  d[2]  = a1x;  d[3]  = a1y;
        d[4]  = a2x;  d[5]  = a2y;  d[6]  = dx01; d[7]  = dy01;
        d[8]  = dx12; d[9]  = dy12; d[10] = dx20; d[11] = dy20;
        d[12] = z0;   d[13] = z1;   d[14] = z2;   d[15] = 1.0f / denom;
        d[16] = 1.0f / l01; d[17] = 1.0f / l12; d[18] = 1.0f / l20;
        d[19] = big ? 1.0f : 0.0f;
    }
    __syncthreads();

    // ---- Phase 2: one pixel per thread, scan all faces, keep top-4 smallest z
    const int pix = blockIdx.x * TPB + tid;      // 0..16575
    if (pix >= NPIX) return;                     // trailing warps exit
    const int pi  = pix >> 7;                    // row
    const int pj  = pix & (IMG - 1);             // col
    const float px = 1.0f - (2.0f * ((float)pj + 0.5f)) * (1.0f / (float)IMG);
    const float py = 1.0f - (2.0f * ((float)pi + 0.5f)) * (1.0f / (float)IMG);

    const float4* fq = (const float4*)sf;

    const unsigned long long SENT = ~0ull;
    unsigned long long s0 = SENT, s1 = SENT, s2 = SENT, s3 = SENT;

#pragma unroll 4
    for (int f = 0; f < NFACE; ++f) {
        FaceEval e = eval_face(fq + f * 5, px, py);
        // Packed key: valid z > EPS > 0 so float bits are order-isomorphic;
        // low 32 bits = face index -> exact lower-index-first top_k tie-break.
        unsigned long long key =
            e.valid ? ((((unsigned long long)__float_as_uint(e.zpix)) << 32) |
                       (unsigned)f)
                    : SENT;
        if (key < s3) {   // rarely taken after warmup -> warp skips insert network
            bool c0 = key < s0, c1 = key < s1, c2 = key < s2;
            unsigned long long n1 = c1 ? (c0 ? s0 : key) : s1;
            unsigned long long n2 = c2 ? (c1 ? s1 : key) : s2;
            unsigned long long n3 = c2 ? s2 : key;
            s0 = c0 ? key : s0;
            s1 = n1; s2 = n2; s3 = n3;
        }
    }

    // ---- Phase 3: epilogue — recompute payload for the <=4 winners and store
    const long long gp = (long long)b * NPIX + pix;
    unsigned long long ss[KTOP] = { s0, s1, s2, s3 };

#pragma unroll
    for (int k = 0; k < KTOP; ++k) {
        long long o = gp * KTOP + k;
        float p2f = -1.0f, zb = -1.0f, bb0 = -1.0f, bb1 = -1.0f, bb2 = -1.0f, ds = -1.0f;
        if (ss[k] != SENT) {
            int f = (int)(unsigned)(ss[k] & 0xffffffffu);
            FaceEval e = eval_face(fq + f * 5, px, py);
            p2f = (float)f;
            zb  = __uint_as_float((unsigned)(ss[k] >> 32));  // exact selected bits
            bb0 = e.b0; bb1 = e.b1; bb2 = e.b2;
            ds  = e.dsign;
        }
        out[o]                    = p2f;
        out[OFF_ZBUF + o]         = zb;
        out[OFF_BARY + 3 * o]     = bb0;
        out[OFF_BARY + 3 * o + 1] = bb1;
        out[OFF_BARY + 3 * o + 2] = bb2;
        out[OFF_DIST + o]         = ds;
    }
}

extern "C" void kernel_launch(void* const* d_in, const int* in_sizes, int n_in,
                              void* d_out, int out_size) {
    const float* verts = (const float*)d_in[0];   // (2, 2000, 3) float32
    const int*   faces = (const int*)d_in[1];     // (800, 3)     int32
    float*       out   = (float*)d_out;

    cudaFuncSetAttribute(raster_kernel,
                         cudaFuncAttributeMaxDynamicSharedMemorySize, SMEM_BYTES);

    dim3 grid(BLKX, NB);   // 148 blocks of 7 warps -> exactly 1 block/SM, balanced
    raster_kernel<<<grid, TPB, SMEM_BYTES>>>(verts, faces, out);
}